// round 12
// baseline (speedup 1.0000x reference)
#include <cuda_runtime.h>
#include <cuda_fp16.h>
#include <cstdint>
#include <cstddef>

#define TDIM 4096
#define HDIM 2048
#define FDIM 7168

// ---------------- GEMM tile config (fp16 mma.sync, pair-staged, persistent) ----------------
#define BM 128
#define BN 256
#define BK 64                         // K per stage; processed in PAIRS (K=128)
#define STG 4                         // 2 pair-buffers
#define AST (BM * BK * 2)             // 16384 B
#define BST (BN * BK * 2)             // 32768 B
#define STB (AST + BST)               // 49152 B
#define SMEMB (STG * STB)             // 196608 B

#define N4X (TDIM * HDIM / 4)         // 2097152
#define N4W (FDIM * HDIM / 4)         // 3670016

// ---------------- scratch (no allocations allowed) ----------------
__device__ __half d_xh[(size_t)TDIM * HDIM];
__device__ __half d_w1h[(size_t)FDIM * HDIM];
__device__ __half d_w3h[(size_t)FDIM * HDIM];
__device__ __half d_w2h[(size_t)HDIM * FDIM];
__device__ __half d_gh[(size_t)TDIM * FDIM];
__device__ __half d_acth[(size_t)TDIM * FDIM];

// ---------------- helpers ----------------
__device__ __forceinline__ uint32_t smem_u32(const void* p) {
    uint32_t a;
    asm("{ .reg .u64 t; cvta.to.shared.u64 t, %1; cvt.u32.u64 %0, t; }" : "=r"(a) : "l"(p));
    return a;
}
__device__ __forceinline__ void cp_async16(uint32_t dst, const void* src) {
    asm volatile("cp.async.cg.shared.global [%0], [%1], 16;\n" :: "r"(dst), "l"(src));
}
__device__ __forceinline__ void cp_commit() { asm volatile("cp.async.commit_group;\n"); }
template <int N>
__device__ __forceinline__ void cp_wait() { asm volatile("cp.async.wait_group %0;\n" :: "n"(N)); }

__device__ __forceinline__ void ldm_x4(uint32_t* r, uint32_t addr) {
    asm volatile("ldmatrix.sync.aligned.m8n8.x4.shared.b16 {%0,%1,%2,%3}, [%4];"
                 : "=r"(r[0]), "=r"(r[1]), "=r"(r[2]), "=r"(r[3]) : "r"(addr));
}
__device__ __forceinline__ void mma_f16(float* d, const uint32_t* a, const uint32_t* b) {
    asm volatile(
        "mma.sync.aligned.m16n8k16.row.col.f32.f16.f16.f32 "
        "{%0,%1,%2,%3}, {%4,%5,%6,%7}, {%8,%9}, {%0,%1,%2,%3};\n"
        : "+f"(d[0]), "+f"(d[1]), "+f"(d[2]), "+f"(d[3])
        : "r"(a[0]), "r"(a[1]), "r"(a[2]), "r"(a[3]), "r"(b[0]), "r"(b[1]));
}
__device__ __forceinline__ float silu_f(float v) {
    return v / (1.0f + __expf(-v));
}

// ---------------- fused convert kernel: x, w1, w3, w2 in one grid ----------------
__global__ void cvt_all_kernel(const float4* __restrict__ x,  uint2* __restrict__ xo,
                               const float4* __restrict__ w1, uint2* __restrict__ w1o,
                               const float4* __restrict__ w3, uint2* __restrict__ w3o,
                               const float4* __restrict__ w2, uint2* __restrict__ w2o) {
    int i = blockIdx.x * blockDim.x + threadIdx.x;
    const float4* src; uint2* dst; int j;
    if (i < N4X)               { src = x;  dst = xo;  j = i; }
    else if (i < N4X + N4W)    { src = w1; dst = w1o; j = i - N4X; }
    else if (i < N4X + 2*N4W)  { src = w3; dst = w3o; j = i - N4X - N4W; }
    else                       { src = w2; dst = w2o; j = i - N4X - 2*N4W; }
    float4 v = src[j];
    __half2 h0 = __floats2half2_rn(v.x, v.y);
    __half2 h1 = __floats2half2_rn(v.z, v.w);
    dst[j] = make_uint2(*reinterpret_cast<uint32_t*>(&h0), *reinterpret_cast<uint32_t*>(&h1));
}

// ---------------- persistent fp16 mma.sync GEMM, pair-staged, scale folding ----------------
// C[m,n] = sum_kb S[n/128, kb] * sum_{k in kb} A[m,k] * B[n,k]
// mode: 0 = fp32 store; 1 = fp16 store; 2 = fp16 store of silu(G)*result (fused SwiGLU).
// Each CTA strides over flattened tiles (bm fastest). Pair p == scale block p.
// Mainloop identical to the validated R10/R11 kernel.
__global__ __launch_bounds__(256, 1)
void gemm_f16(const __half* __restrict__ A,
              const __half* __restrict__ B, const float* __restrict__ S, void* __restrict__ Cv,
              const __half* __restrict__ G,
              int M, int N, int K, int mode)
{
    extern __shared__ char smem[];
    const uint32_t sb = smem_u32(smem);
    const int tid = threadIdx.x;
    const int wid = tid >> 5, lane = tid & 31;
    const int wm = wid & 1, wn = wid >> 1;       // 2 x 4 warps, 64x64 warp tiles
    const int mat = lane >> 3, mr = lane & 7;
    const int g = lane >> 2, t4 = lane & 3;

    const int GM = M >> 7;              // M/128 tiles
    const int GN = N >> 8;              // N/256 tiles
    const int NP = K >> 7;              // K=128 pairs == scale blocks
    const int total = GM * GN;

    for (int t = blockIdx.x; t < total; t += gridDim.x) {
        const int bn = t / GM;
        const int bm = t - bn * GM;

        const __half* Ab = A + (size_t)bm * BM * K;
        const __half* Bb = B + (size_t)bn * BN * K;
        const float* Srow = S + (size_t)(bn * 2 + (wn >> 1)) * NP;

        // load both 64-k stages of pair p into buffers 2*(p&1), 2*(p&1)+1; ONE commit
        auto load_pair = [&](int p) {
            #pragma unroll
            for (int h = 0; h < 2; h++) {
                const uint32_t ab = sb + ((p & 1) * 2 + h) * STB;
                const uint32_t bb = ab + AST;
                const int k0 = (p << 7) + (h << 6);
                #pragma unroll
                for (int tt = 0; tt < 4; tt++) {        // A: 1024 x 16B chunks
                    int idx = tid + tt * 256;
                    int row = idx >> 3, c = idx & 7;
                    uint32_t off = (uint32_t)(row << 7) + (c << 4);
                    uint32_t sw = off ^ ((off >> 3) & 0x70);
                    cp_async16(ab + sw, Ab + (size_t)row * K + k0 + c * 8);
                }
                #pragma unroll
                for (int tt = 0; tt < 8; tt++) {        // B: 2048 x 16B chunks
                    int idx = tid + tt * 256;
                    int row = idx >> 3, c = idx & 7;
                    uint32_t off = (uint32_t)(row << 7) + (c << 4);
                    uint32_t sw = off ^ ((off >> 3) & 0x70);
                    cp_async16(bb + sw, Bb + (size_t)row * K + k0 + c * 8);
                }
            }
            cp_commit();
        };

        float acc[4][8][4];
        #pragma unroll
        for (int mt = 0; mt < 4; mt++)
            #pragma unroll
            for (int nt = 0; nt < 8; nt++)
                #pragma unroll
                for (int i = 0; i < 4; i++) acc[mt][nt][i] = 0.0f;

        load_pair(0);
        float s_cur = __ldg(Srow);

        for (int p = 0; p < NP; p++) {
            if (p) {                    // entering new scale block (== new pair)
                float sn = __ldg(Srow + p);
                float rr = s_cur / sn;
                s_cur = sn;
                #pragma unroll
                for (int mt = 0; mt < 4; mt++)
                    #pragma unroll
                    for (int nt = 0; nt < 8; nt++)
                        #pragma unroll
                        for (int i = 0; i < 4; i++) acc[mt][nt][i] *= rr;
            }

            cp_wait<0>();               // pair p resident (only group in flight)
            __syncthreads();            // all warps done with pair p-1's buffers

            if (p + 1 < NP) load_pair(p + 1);   // overwrites pair p-1's buffers: safe

            #pragma unroll
            for (int h = 0; h < 2; h++) {
                const uint32_t ab = sb + ((p & 1) * 2 + h) * STB;
                const uint32_t bb = ab + AST;
                #pragma unroll
                for (int ks = 0; ks < 4; ks++) {
                    uint32_t af[4][4], bf[4][4];
                    #pragma unroll
                    for (int mt = 0; mt < 4; mt++) {
                        int row = wm * 64 + mt * 16 + (mat & 1) * 8 + mr;
                        uint32_t off = (uint32_t)(row << 7) + ks * 32 + (mat >> 1) * 16;
                        uint32_t sw = off ^ ((off >> 3) & 0x70);
                        ldm_x4(af[mt], ab + sw);
                    }
                    #pragma unroll
                    for (int bq = 0; bq < 4; bq++) {
                        int nrow = wn * 64 + (bq * 2 + (mat >> 1)) * 8 + mr;
                        uint32_t off = (uint32_t)(nrow << 7) + ks * 32 + (mat & 1) * 16;
                        uint32_t sw = off ^ ((off >> 3) & 0x70);
                        ldm_x4(bf[bq], bb + sw);
                    }
                    #pragma unroll
                    for (int mt = 0; mt < 4; mt++)
                        #pragma unroll
                        for (int nt = 0; nt < 8; nt++)
                            mma_f16(acc[mt][nt], af[mt], &bf[nt >> 1][(nt & 1) * 2]);
                }
            }
        }

        // epilogue: scale by this warp's last block S; mode-dependent store
        if (mode == 1) {
            __half* Ch = (__half*)Cv;
            #pragma unroll
            for (int mt = 0; mt < 4; mt++) {
                int r0 = bm * BM + wm * 64 + mt * 16 + g;
                #pragma unroll
                for (int nt = 0; nt < 8; nt++) {
                    int c0 = bn * BN + wn * 64 + nt * 8 + t4 * 2;
                    __half2 h0 = __floats2half2_rn(acc[mt][nt][0] * s_cur, acc[mt][nt][1] * s_cur);
                    __half2 h1 = __floats2half2_rn(acc[mt][nt][2] * s_cur, acc[mt][nt][3] * s_cur);
                    *reinterpret_cast<__half2*>(&Ch[(size_t)r0 * N + c0]) = h0;
                    *reinterpret_cast<__half2*>(&Ch[(size_t)(r0 + 8) * N + c0]) = h1;
                }
            }
        } else if (mode == 2) {
            __half* Ch = (__half*)Cv;
            #pragma unroll
            for (int mt = 0; mt < 4; mt++) {
                int r0 = bm * BM + wm * 64 + mt * 16 + g;
                #pragma unroll
                for (int nt = 0; nt < 8; nt++) {
                    int c0 = bn * BN + wn * 64 + nt * 8 + t4 * 2;
                    __half2 g0 = *reinterpret_cast<const __half2*>(&G[(size_t)r0 * N + c0]);
                    __half2 g1 = *reinterpret_cast<const __half2*>(&G[(size_t)(r0 + 8) * N + c0]);
                    float v00 = silu_f(__low2float(g0))  * (acc[mt][nt][0] * s_cur);
                    float v01 = silu_f(__high2float(g0)) * (acc[mt][nt][1] * s_cur);
                    float v10 = silu_f(__low2float(g1))  * (acc[mt][nt][2] * s_cur);
                    float v11 = silu_f(__high2float(g1)) * (acc[mt][nt][3] * s_cur);
                    __half2 h0 = __floats2half2_rn(v00, v01);
                    __half2 h1 = __floats2half2_rn(v10, v11);
                    *reinterpret_cast<__half2*>(&Ch[(size_t)r0 * N + c0]) = h0;
                    *reinterpret_cast<__half2*>(&Ch[(size_t)(r0 + 8) * N + c0]) = h1;
                }
            }
        } else {
            float* Cf = (float*)Cv;
            #pragma unroll
            for (int mt = 0; mt < 4; mt++) {
                int r0 = bm * BM + wm * 64 + mt * 16 + g;
                #pragma unroll
                for (int nt = 0; nt < 8; nt++) {
                    int c0 = bn * BN + wn * 64 + nt * 8 + t4 * 2;
                    float2 v0 = make_float2(acc[mt][nt][0] * s_cur, acc[mt][nt][1] * s_cur);
                    float2 v1 = make_float2(acc[mt][nt][2] * s_cur, acc[mt][nt][3] * s_cur);
                    *reinterpret_cast<float2*>(&Cf[(size_t)r0 * N + c0]) = v0;
                    *reinterpret_cast<float2*>(&Cf[(size_t)(r0 + 8) * N + c0]) = v1;
                }
            }
        }
    }
}

// ---------------- launch ----------------
extern "C" void kernel_launch(void* const* d_in, const int* in_sizes, int n_in,
                              void* d_out, int out_size) {
    (void)in_sizes; (void)n_in; (void)out_size;
    const float* x   = (const float*)d_in[0];
    const float* w1q = (const float*)d_in[1];
    const float* w1s = (const float*)d_in[2];
    const float* w3q = (const float*)d_in[3];
    const float* w3s = (const float*)d_in[4];
    const float* w2q = (const float*)d_in[5];
    const float* w2s = (const float*)d_in[6];
    float* out = (float*)d_out;

    __half *xh, *w1h, *w3h, *w2h, *gh, *acth;
    cudaGetSymbolAddress((void**)&xh,   d_xh);
    cudaGetSymbolAddress((void**)&w1h,  d_w1h);
    cudaGetSymbolAddress((void**)&w3h,  d_w3h);
    cudaGetSymbolAddress((void**)&w2h,  d_w2h);
    cudaGetSymbolAddress((void**)&gh,   d_gh);
    cudaGetSymbolAddress((void**)&acth, d_acth);

    int nsm = 148;
    cudaDeviceGetAttribute(&nsm, cudaDevAttrMultiProcessorCount, 0);

    cudaFuncSetAttribute(gemm_f16, cudaFuncAttributeMaxDynamicSharedMemorySize, SMEMB);

    // one fused convert launch: x + w1 + w3 + w2
    const int n4tot = N4X + 3 * N4W;
    cvt_all_kernel<<<(n4tot + 255) / 256, 256>>>(
        (const float4*)x,   (uint2*)xh,
        (const float4*)w1q, (uint2*)w1h,
        (const float4*)w3q, (uint2*)w3h,
        (const float4*)w2q, (uint2*)w2h);

    // g = x @ w1^T  (fp16 out, persistent)
    {
        const int tiles = (TDIM / BM) * (FDIM / BN);
        const int grid = tiles < nsm ? tiles : nsm;
        gemm_f16<<<grid, 256, SMEMB>>>(xh, w1h, w1s, gh, nullptr,
                                       TDIM, FDIM, HDIM, 1);
    }

    // act = silu(g) * (x @ w3^T)  (fused epilogue, fp16 out, persistent)
    {
        const int tiles = (TDIM / BM) * (FDIM / BN);
        const int grid = tiles < nsm ? tiles : nsm;
        gemm_f16<<<grid, 256, SMEMB>>>(xh, w3h, w3s, acth, gh,
                                       TDIM, FDIM, HDIM, 2);
    }

    // out = act @ w2^T  (fp32 out, persistent)
    {
        const int tiles = (TDIM / BM) * (HDIM / BN);
        const int grid = tiles < nsm ? tiles : nsm;
        gemm_f16<<<grid, 256, SMEMB>>>(acth, w2h, w2s, out, nullptr,
                                       TDIM, HDIM, FDIM, 0);
    }
}

// round 13
// speedup vs baseline: 1.0774x; 1.0774x over previous
#include <cuda_runtime.h>
#include <cuda_fp16.h>
#include <cstdint>
#include <cstddef>

#define TDIM 4096
#define HDIM 2048
#define FDIM 7168

// ---------------- GEMM tile config (fp16 mma.sync, pair-staged, persistent) ----------------
#define BM 128
#define BN 256
#define BK 64                         // K per stage; processed in PAIRS (K=128)
#define STG 4                         // 2 pair-buffers
#define AST (BM * BK * 2)             // 16384 B
#define BST (BN * BK * 2)             // 32768 B
#define STB (AST + BST)               // 49152 B
#define SMEMB (STG * STB)             // 196608 B

#define N4X (TDIM * HDIM / 4)         // 2097152
#define N4W (FDIM * HDIM / 4)         // 3670016

// ---------------- scratch (no allocations allowed) ----------------
__device__ __half d_xh[(size_t)TDIM * HDIM];
__device__ __half d_w1h[(size_t)FDIM * HDIM];
__device__ __half d_w3h[(size_t)FDIM * HDIM];
__device__ __half d_w2h[(size_t)HDIM * FDIM];
__device__ __half d_gh[(size_t)TDIM * FDIM];
__device__ __half d_uh[(size_t)TDIM * FDIM];
__device__ __half d_acth[(size_t)TDIM * FDIM];

// ---------------- helpers ----------------
__device__ __forceinline__ uint32_t smem_u32(const void* p) {
    uint32_t a;
    asm("{ .reg .u64 t; cvta.to.shared.u64 t, %1; cvt.u32.u64 %0, t; }" : "=r"(a) : "l"(p));
    return a;
}
__device__ __forceinline__ void cp_async16(uint32_t dst, const void* src) {
    asm volatile("cp.async.cg.shared.global [%0], [%1], 16;\n" :: "r"(dst), "l"(src));
}
__device__ __forceinline__ void cp_commit() { asm volatile("cp.async.commit_group;\n"); }
template <int N>
__device__ __forceinline__ void cp_wait() { asm volatile("cp.async.wait_group %0;\n" :: "n"(N)); }

__device__ __forceinline__ void ldm_x4(uint32_t* r, uint32_t addr) {
    asm volatile("ldmatrix.sync.aligned.m8n8.x4.shared.b16 {%0,%1,%2,%3}, [%4];"
                 : "=r"(r[0]), "=r"(r[1]), "=r"(r[2]), "=r"(r[3]) : "r"(addr));
}
__device__ __forceinline__ void mma_f16(float* d, const uint32_t* a, const uint32_t* b) {
    asm volatile(
        "mma.sync.aligned.m16n8k16.row.col.f32.f16.f16.f32 "
        "{%0,%1,%2,%3}, {%4,%5,%6,%7}, {%8,%9}, {%0,%1,%2,%3};\n"
        : "+f"(d[0]), "+f"(d[1]), "+f"(d[2]), "+f"(d[3])
        : "r"(a[0]), "r"(a[1]), "r"(a[2]), "r"(a[3]), "r"(b[0]), "r"(b[1]));
}

// ---------------- fused convert kernel: x, w1, w3, w2 in one grid ----------------
__global__ void cvt_all_kernel(const float4* __restrict__ x,  uint2* __restrict__ xo,
                               const float4* __restrict__ w1, uint2* __restrict__ w1o,
                               const float4* __restrict__ w3, uint2* __restrict__ w3o,
                               const float4* __restrict__ w2, uint2* __restrict__ w2o) {
    int i = blockIdx.x * blockDim.x + threadIdx.x;
    const float4* src; uint2* dst; int j;
    if (i < N4X)               { src = x;  dst = xo;  j = i; }
    else if (i < N4X + N4W)    { src = w1; dst = w1o; j = i - N4X; }
    else if (i < N4X + 2*N4W)  { src = w3; dst = w3o; j = i - N4X - N4W; }
    else                       { src = w2; dst = w2o; j = i - N4X - 2*N4W; }
    float4 v = src[j];
    __half2 h0 = __floats2half2_rn(v.x, v.y);
    __half2 h1 = __floats2half2_rn(v.z, v.w);
    dst[j] = make_uint2(*reinterpret_cast<uint32_t*>(&h0), *reinterpret_cast<uint32_t*>(&h1));
}

// ---------------- silu-mul on fp16 inputs ----------------
__global__ void silu_mul_h_kernel(const uint2* __restrict__ g, const uint2* __restrict__ u,
                                  uint2* __restrict__ out, int n4) {
    int i = blockIdx.x * blockDim.x + threadIdx.x;
    if (i < n4) {
        uint2 gv = g[i], uv = u[i];
        __half2 g0 = *reinterpret_cast<__half2*>(&gv.x);
        __half2 g1 = *reinterpret_cast<__half2*>(&gv.y);
        __half2 u0 = *reinterpret_cast<__half2*>(&uv.x);
        __half2 u1 = *reinterpret_cast<__half2*>(&uv.y);
        float a0 = __low2float(g0), a1 = __high2float(g0);
        float a2 = __low2float(g1), a3 = __high2float(g1);
        float r0 = a0 / (1.0f + __expf(-a0)) * __low2float(u0);
        float r1 = a1 / (1.0f + __expf(-a1)) * __high2float(u0);
        float r2 = a2 / (1.0f + __expf(-a2)) * __low2float(u1);
        float r3 = a3 / (1.0f + __expf(-a3)) * __high2float(u1);
        __half2 h0 = __floats2half2_rn(r0, r1);
        __half2 h1 = __floats2half2_rn(r2, r3);
        out[i] = make_uint2(*reinterpret_cast<uint32_t*>(&h0), *reinterpret_cast<uint32_t*>(&h1));
    }
}

// ---------------- persistent fp16 mma.sync GEMM, pair-staged, scale folding ----------------
// C[m,n] = sum_kb S[n/128, kb] * sum_{k in kb} A[m,k] * B[n,k]
// The per-pair accumulator fold (acc *= s_prev/s_next) is interleaved into the
// FIRST mma group of the pair (h=0,ks=0): each acc tile is scaled right before
// its mma, so FMULs of tile i+1 hide under the HMMA shadow of tile i.
// rr == 1.0 on the first pair (exact no-op). Otherwise identical to R11.
__global__ __launch_bounds__(256, 1)
void gemm_f16(const __half* __restrict__ A,
              const __half* __restrict__ B0, const float* __restrict__ S0, void* __restrict__ C0,
              const __half* __restrict__ B1, const float* __restrict__ S1, void* __restrict__ C1,
              int M, int N, int K, int out_half, int nz)
{
    extern __shared__ char smem[];
    const uint32_t sb = smem_u32(smem);
    const int tid = threadIdx.x;
    const int wid = tid >> 5, lane = tid & 31;
    const int wm = wid & 1, wn = wid >> 1;       // 2 x 4 warps, 64x64 warp tiles
    const int mat = lane >> 3, mr = lane & 7;
    const int g = lane >> 2, t4 = lane & 3;

    const int GM = M >> 7;              // M/128 tiles
    const int GN = N >> 8;              // N/256 tiles
    const int NP = K >> 7;              // K=128 pairs == scale blocks
    const int total = GM * GN * nz;

    for (int t = blockIdx.x; t < total; t += gridDim.x) {
        const int z  = t / (GM * GN);
        const int r_ = t - z * (GM * GN);
        const int bn = r_ / GM;
        const int bm = r_ - bn * GM;

        const __half* B = z ? B1 : B0;
        const float*  S = z ? S1 : S0;
        void*         Cv = z ? C1 : C0;

        const __half* Ab = A + (size_t)bm * BM * K;
        const __half* Bb = B + (size_t)bn * BN * K;
        const float* Srow = S + (size_t)(bn * 2 + (wn >> 1)) * NP;

        // load both 64-k stages of pair p into buffers 2*(p&1), 2*(p&1)+1; ONE commit
        auto load_pair = [&](int p) {
            #pragma unroll
            for (int h = 0; h < 2; h++) {
                const uint32_t ab = sb + ((p & 1) * 2 + h) * STB;
                const uint32_t bb = ab + AST;
                const int k0 = (p << 7) + (h << 6);
                #pragma unroll
                for (int tt = 0; tt < 4; tt++) {        // A: 1024 x 16B chunks
                    int idx = tid + tt * 256;
                    int row = idx >> 3, c = idx & 7;
                    uint32_t off = (uint32_t)(row << 7) + (c << 4);
                    uint32_t sw = off ^ ((off >> 3) & 0x70);
                    cp_async16(ab + sw, Ab + (size_t)row * K + k0 + c * 8);
                }
                #pragma unroll
                for (int tt = 0; tt < 8; tt++) {        // B: 2048 x 16B chunks
                    int idx = tid + tt * 256;
                    int row = idx >> 3, c = idx & 7;
                    uint32_t off = (uint32_t)(row << 7) + (c << 4);
                    uint32_t sw = off ^ ((off >> 3) & 0x70);
                    cp_async16(bb + sw, Bb + (size_t)row * K + k0 + c * 8);
                }
            }
            cp_commit();
        };

        float acc[4][8][4];
        #pragma unroll
        for (int mt = 0; mt < 4; mt++)
            #pragma unroll
            for (int nt = 0; nt < 8; nt++)
                #pragma unroll
                for (int i = 0; i < 4; i++) acc[mt][nt][i] = 0.0f;

        load_pair(0);
        float s_cur = __ldg(Srow);

        for (int p = 0; p < NP; p++) {
            float rr = 1.0f;
            if (p) {                    // entering new scale block (== new pair)
                float sn = __ldg(Srow + p);
                rr = s_cur / sn;
                s_cur = sn;
            }

            cp_wait<0>();               // pair p resident (only group in flight)
            __syncthreads();            // all warps done with pair p-1's buffers

            if (p + 1 < NP) load_pair(p + 1);   // overwrites pair p-1's buffers: safe

            #pragma unroll
            for (int h = 0; h < 2; h++) {
                const uint32_t ab = sb + ((p & 1) * 2 + h) * STB;
                const uint32_t bb = ab + AST;
                #pragma unroll
                for (int ks = 0; ks < 4; ks++) {
                    uint32_t af[4][4], bf[4][4];
                    #pragma unroll
                    for (int mt = 0; mt < 4; mt++) {
                        int row = wm * 64 + mt * 16 + (mat & 1) * 8 + mr;
                        uint32_t off = (uint32_t)(row << 7) + ks * 32 + (mat >> 1) * 16;
                        uint32_t sw = off ^ ((off >> 3) & 0x70);
                        ldm_x4(af[mt], ab + sw);
                    }
                    #pragma unroll
                    for (int bq = 0; bq < 4; bq++) {
                        int nrow = wn * 64 + (bq * 2 + (mat >> 1)) * 8 + mr;
                        uint32_t off = (uint32_t)(nrow << 7) + ks * 32 + (mat & 1) * 16;
                        uint32_t sw = off ^ ((off >> 3) & 0x70);
                        ldm_x4(bf[bq], bb + sw);
                    }
                    if (h == 0 && ks == 0) {
                        // fold interleaved with first mma group of the pair:
                        // FMULs of tile i+1 issue under the HMMA shadow of tile i
                        #pragma unroll
                        for (int mt = 0; mt < 4; mt++)
                            #pragma unroll
                            for (int nt = 0; nt < 8; nt++) {
                                acc[mt][nt][0] *= rr;
                                acc[mt][nt][1] *= rr;
                                acc[mt][nt][2] *= rr;
                                acc[mt][nt][3] *= rr;
                                mma_f16(acc[mt][nt], af[mt], &bf[nt >> 1][(nt & 1) * 2]);
                            }
                    } else {
                        #pragma unroll
                        for (int mt = 0; mt < 4; mt++)
                            #pragma unroll
                            for (int nt = 0; nt < 8; nt++)
                                mma_f16(acc[mt][nt], af[mt], &bf[nt >> 1][(nt & 1) * 2]);
                    }
                }
            }
        }

        // epilogue: scale by this warp's last block S; fp16 or fp32 stores
        if (out_half) {
            __half* Ch = (__half*)Cv;
            #pragma unroll
            for (int mt = 0; mt < 4; mt++) {
                int r0 = bm * BM + wm * 64 + mt * 16 + g;
                #pragma unroll
                for (int nt = 0; nt < 8; nt++) {
                    int c0 = bn * BN + wn * 64 + nt * 8 + t4 * 2;
                    __half2 h0 = __floats2half2_rn(acc[mt][nt][0] * s_cur, acc[mt][nt][1] * s_cur);
                    __half2 h1 = __floats2half2_rn(acc[mt][nt][2] * s_cur, acc[mt][nt][3] * s_cur);
                    *reinterpret_cast<__half2*>(&Ch[(size_t)r0 * N + c0]) = h0;
                    *reinterpret_cast<__half2*>(&Ch[(size_t)(r0 + 8) * N + c0]) = h1;
                }
            }
        } else {
            float* Cf = (float*)Cv;
            #pragma unroll
            for (int mt = 0; mt < 4; mt++) {
                int r0 = bm * BM + wm * 64 + mt * 16 + g;
                #pragma unroll
                for (int nt = 0; nt < 8; nt++) {
                    int c0 = bn * BN + wn * 64 + nt * 8 + t4 * 2;
                    float2 v0 = make_float2(acc[mt][nt][0] * s_cur, acc[mt][nt][1] * s_cur);
                    float2 v1 = make_float2(acc[mt][nt][2] * s_cur, acc[mt][nt][3] * s_cur);
                    *reinterpret_cast<float2*>(&Cf[(size_t)r0 * N + c0]) = v0;
                    *reinterpret_cast<float2*>(&Cf[(size_t)(r0 + 8) * N + c0]) = v1;
                }
            }
        }
    }
}

// ---------------- launch ----------------
extern "C" void kernel_launch(void* const* d_in, const int* in_sizes, int n_in,
                              void* d_out, int out_size) {
    (void)in_sizes; (void)n_in; (void)out_size;
    const float* x   = (const float*)d_in[0];
    const float* w1q = (const float*)d_in[1];
    const float* w1s = (const float*)d_in[2];
    const float* w3q = (const float*)d_in[3];
    const float* w3s = (const float*)d_in[4];
    const float* w2q = (const float*)d_in[5];
    const float* w2s = (const float*)d_in[6];
    float* out = (float*)d_out;

    __half *xh, *w1h, *w3h, *w2h, *gh, *uh, *acth;
    cudaGetSymbolAddress((void**)&xh,   d_xh);
    cudaGetSymbolAddress((void**)&w1h,  d_w1h);
    cudaGetSymbolAddress((void**)&w3h,  d_w3h);
    cudaGetSymbolAddress((void**)&w2h,  d_w2h);
    cudaGetSymbolAddress((void**)&gh,   d_gh);
    cudaGetSymbolAddress((void**)&uh,   d_uh);
    cudaGetSymbolAddress((void**)&acth, d_acth);

    int nsm = 148;
    cudaDeviceGetAttribute(&nsm, cudaDevAttrMultiProcessorCount, 0);

    cudaFuncSetAttribute(gemm_f16, cudaFuncAttributeMaxDynamicSharedMemorySize, SMEMB);

    // one fused convert launch: x + w1 + w3 + w2
    const int n4tot = N4X + 3 * N4W;
    cvt_all_kernel<<<(n4tot + 255) / 256, 256>>>(
        (const float4*)x,   (uint2*)xh,
        (const float4*)w1q, (uint2*)w1h,
        (const float4*)w3q, (uint2*)w3h,
        (const float4*)w2q, (uint2*)w2h);

    // g = x@w1^T and u = x@w3^T in ONE persistent launch (fp16 outputs)
    {
        const int tiles = (TDIM / BM) * (FDIM / BN) * 2;
        const int grid = tiles < nsm ? tiles : nsm;
        gemm_f16<<<grid, 256, SMEMB>>>(
            xh, w1h, w1s, gh, w3h, w3s, uh, TDIM, FDIM, HDIM, 1, 2);
    }

    const int n4f = TDIM * FDIM / 4;
    silu_mul_h_kernel<<<(n4f + 255) / 256, 256>>>(
        (const uint2*)gh, (const uint2*)uh, (uint2*)acth, n4f);

    // out = act @ w2^T  (fp32 out, persistent)
    {
        const int tiles = (TDIM / BM) * (HDIM / BN);
        const int grid = tiles < nsm ? tiles : nsm;
        gemm_f16<<<grid, 256, SMEMB>>>(
            acth, w2h, w2s, out, w2h, w2s, out, TDIM, HDIM, FDIM, 0, 1);
    }
}

// round 14
// speedup vs baseline: 1.0802x; 1.0026x over previous
#include <cuda_runtime.h>
#include <cuda_fp16.h>
#include <cstdint>
#include <cstddef>

#define TDIM 4096
#define HDIM 2048
#define FDIM 7168

// ---------------- GEMM tile config (fp16 mma.sync, pair-staged, persistent) ----------------
#define BM 128
#define BN 256
#define BK 64                         // K per stage; processed in PAIRS (K=128)
#define STG 4                         // 2 pair-buffers
#define AST (BM * BK * 2)             // 16384 B
#define BST (BN * BK * 2)             // 32768 B
#define STB (AST + BST)               // 49152 B
#define SMEMB (STG * STB)             // 196608 B

#define N4X (TDIM * HDIM / 4)         // 2097152
#define N4W (FDIM * HDIM / 4)         // 3670016

// ---------------- scratch (no allocations allowed) ----------------
__device__ __half d_xh[(size_t)TDIM * HDIM];
__device__ __half d_w1h[(size_t)FDIM * HDIM];
__device__ __half d_w3h[(size_t)FDIM * HDIM];
__device__ __half d_w2h[(size_t)HDIM * FDIM];
__device__ __half d_gh[(size_t)TDIM * FDIM];
__device__ __half d_uh[(size_t)TDIM * FDIM];
__device__ __half d_acth[(size_t)TDIM * FDIM];

// ---------------- helpers ----------------
__device__ __forceinline__ uint32_t smem_u32(const void* p) {
    uint32_t a;
    asm("{ .reg .u64 t; cvta.to.shared.u64 t, %1; cvt.u32.u64 %0, t; }" : "=r"(a) : "l"(p));
    return a;
}
__device__ __forceinline__ void cp_async16(uint32_t dst, const void* src) {
    asm volatile("cp.async.cg.shared.global [%0], [%1], 16;\n" :: "r"(dst), "l"(src));
}
__device__ __forceinline__ void cp_commit() { asm volatile("cp.async.commit_group;\n"); }
template <int N>
__device__ __forceinline__ void cp_wait() { asm volatile("cp.async.wait_group %0;\n" :: "n"(N)); }

__device__ __forceinline__ void ldm_x4(uint32_t* r, uint32_t addr) {
    asm volatile("ldmatrix.sync.aligned.m8n8.x4.shared.b16 {%0,%1,%2,%3}, [%4];"
                 : "=r"(r[0]), "=r"(r[1]), "=r"(r[2]), "=r"(r[3]) : "r"(addr));
}
__device__ __forceinline__ void mma_f16(float* d, const uint32_t* a, const uint32_t* b) {
    asm volatile(
        "mma.sync.aligned.m16n8k16.row.col.f32.f16.f16.f32 "
        "{%0,%1,%2,%3}, {%4,%5,%6,%7}, {%8,%9}, {%0,%1,%2,%3};\n"
        : "+f"(d[0]), "+f"(d[1]), "+f"(d[2]), "+f"(d[3])
        : "r"(a[0]), "r"(a[1]), "r"(a[2]), "r"(a[3]), "r"(b[0]), "r"(b[1]));
}

// ---------------- fused convert kernel: x, w1, w3, w2; 4 float4 per thread ----------------
__device__ __forceinline__ void cvt_one(const float4* __restrict__ x,  uint2* __restrict__ xo,
                                        const float4* __restrict__ w1, uint2* __restrict__ w1o,
                                        const float4* __restrict__ w3, uint2* __restrict__ w3o,
                                        const float4* __restrict__ w2, uint2* __restrict__ w2o,
                                        int i) {
    const float4* src; uint2* dst; int j;
    if (i < N4X)               { src = x;  dst = xo;  j = i; }
    else if (i < N4X + N4W)    { src = w1; dst = w1o; j = i - N4X; }
    else if (i < N4X + 2*N4W)  { src = w3; dst = w3o; j = i - N4X - N4W; }
    else                       { src = w2; dst = w2o; j = i - N4X - 2*N4W; }
    float4 v = src[j];
    __half2 h0 = __floats2half2_rn(v.x, v.y);
    __half2 h1 = __floats2half2_rn(v.z, v.w);
    dst[j] = make_uint2(*reinterpret_cast<uint32_t*>(&h0), *reinterpret_cast<uint32_t*>(&h1));
}

__global__ void cvt_all_kernel(const float4* __restrict__ x,  uint2* __restrict__ xo,
                               const float4* __restrict__ w1, uint2* __restrict__ w1o,
                               const float4* __restrict__ w3, uint2* __restrict__ w3o,
                               const float4* __restrict__ w2, uint2* __restrict__ w2o,
                               int n4) {
    int base = blockIdx.x * (blockDim.x * 4) + threadIdx.x;
    #pragma unroll
    for (int k = 0; k < 4; k++) {
        int i = base + k * blockDim.x;          // 4 independent coalesced loads in flight
        if (i < n4) cvt_one(x, xo, w1, w1o, w3, w3o, w2, w2o, i);
    }
}

// ---------------- silu-mul on fp16 inputs; 4 uint2 per thread ----------------
__device__ __forceinline__ void silu_one(const uint2* __restrict__ g, const uint2* __restrict__ u,
                                         uint2* __restrict__ out, int i) {
    uint2 gv = g[i], uv = u[i];
    __half2 g0 = *reinterpret_cast<__half2*>(&gv.x);
    __half2 g1 = *reinterpret_cast<__half2*>(&gv.y);
    __half2 u0 = *reinterpret_cast<__half2*>(&uv.x);
    __half2 u1 = *reinterpret_cast<__half2*>(&uv.y);
    float a0 = __low2float(g0), a1 = __high2float(g0);
    float a2 = __low2float(g1), a3 = __high2float(g1);
    float r0 = a0 / (1.0f + __expf(-a0)) * __low2float(u0);
    float r1 = a1 / (1.0f + __expf(-a1)) * __high2float(u0);
    float r2 = a2 / (1.0f + __expf(-a2)) * __low2float(u1);
    float r3 = a3 / (1.0f + __expf(-a3)) * __high2float(u1);
    __half2 h0 = __floats2half2_rn(r0, r1);
    __half2 h1 = __floats2half2_rn(r2, r3);
    out[i] = make_uint2(*reinterpret_cast<uint32_t*>(&h0), *reinterpret_cast<uint32_t*>(&h1));
}

__global__ void silu_mul_h_kernel(const uint2* __restrict__ g, const uint2* __restrict__ u,
                                  uint2* __restrict__ out, int n4) {
    int base = blockIdx.x * (blockDim.x * 4) + threadIdx.x;
    #pragma unroll
    for (int k = 0; k < 4; k++) {
        int i = base + k * blockDim.x;
        if (i < n4) silu_one(g, u, out, i);
    }
}

// ---------------- persistent fp16 mma.sync GEMM, pair-staged, scale folding ----------------
// C[m,n] = sum_kb S[n/128, kb] * sum_{k in kb} A[m,k] * B[n,k]
// The per-pair accumulator fold (acc *= s_prev/s_next) is interleaved into the
// FIRST mma group of the pair (h=0,ks=0): each acc tile is scaled right before
// its mma, so FMULs of tile i+1 hide under the HMMA shadow of tile i.
// rr == 1.0 on the first pair (exact no-op). Byte-identical to the R13 kernel.
__global__ __launch_bounds__(256, 1)
void gemm_f16(const __half* __restrict__ A,
              const __half* __restrict__ B0, const float* __restrict__ S0, void* __restrict__ C0,
              const __half* __restrict__ B1, const float* __restrict__ S1, void* __restrict__ C1,
              int M, int N, int K, int out_half, int nz)
{
    extern __shared__ char smem[];
    const uint32_t sb = smem_u32(smem);
    const int tid = threadIdx.x;
    const int wid = tid >> 5, lane = tid & 31;
    const int wm = wid & 1, wn = wid >> 1;       // 2 x 4 warps, 64x64 warp tiles
    const int mat = lane >> 3, mr = lane & 7;
    const int g = lane >> 2, t4 = lane & 3;

    const int GM = M >> 7;              // M/128 tiles
    const int GN = N >> 8;              // N/256 tiles
    const int NP = K >> 7;              // K=128 pairs == scale blocks
    const int total = GM * GN * nz;

    for (int t = blockIdx.x; t < total; t += gridDim.x) {
        const int z  = t / (GM * GN);
        const int r_ = t - z * (GM * GN);
        const int bn = r_ / GM;
        const int bm = r_ - bn * GM;

        const __half* B = z ? B1 : B0;
        const float*  S = z ? S1 : S0;
        void*         Cv = z ? C1 : C0;

        const __half* Ab = A + (size_t)bm * BM * K;
        const __half* Bb = B + (size_t)bn * BN * K;
        const float* Srow = S + (size_t)(bn * 2 + (wn >> 1)) * NP;

        // load both 64-k stages of pair p into buffers 2*(p&1), 2*(p&1)+1; ONE commit
        auto load_pair = [&](int p) {
            #pragma unroll
            for (int h = 0; h < 2; h++) {
                const uint32_t ab = sb + ((p & 1) * 2 + h) * STB;
                const uint32_t bb = ab + AST;
                const int k0 = (p << 7) + (h << 6);
                #pragma unroll
                for (int tt = 0; tt < 4; tt++) {        // A: 1024 x 16B chunks
                    int idx = tid + tt * 256;
                    int row = idx >> 3, c = idx & 7;
                    uint32_t off = (uint32_t)(row << 7) + (c << 4);
                    uint32_t sw = off ^ ((off >> 3) & 0x70);
                    cp_async16(ab + sw, Ab + (size_t)row * K + k0 + c * 8);
                }
                #pragma unroll
                for (int tt = 0; tt < 8; tt++) {        // B: 2048 x 16B chunks
                    int idx = tid + tt * 256;
                    int row = idx >> 3, c = idx & 7;
                    uint32_t off = (uint32_t)(row << 7) + (c << 4);
                    uint32_t sw = off ^ ((off >> 3) & 0x70);
                    cp_async16(bb + sw, Bb + (size_t)row * K + k0 + c * 8);
                }
            }
            cp_commit();
        };

        float acc[4][8][4];
        #pragma unroll
        for (int mt = 0; mt < 4; mt++)
            #pragma unroll
            for (int nt = 0; nt < 8; nt++)
                #pragma unroll
                for (int i = 0; i < 4; i++) acc[mt][nt][i] = 0.0f;

        load_pair(0);
        float s_cur = __ldg(Srow);

        for (int p = 0; p < NP; p++) {
            float rr = 1.0f;
            if (p) {                    // entering new scale block (== new pair)
                float sn = __ldg(Srow + p);
                rr = s_cur / sn;
                s_cur = sn;
            }

            cp_wait<0>();               // pair p resident (only group in flight)
            __syncthreads();            // all warps done with pair p-1's buffers

            if (p + 1 < NP) load_pair(p + 1);   // overwrites pair p-1's buffers: safe

            #pragma unroll
            for (int h = 0; h < 2; h++) {
                const uint32_t ab = sb + ((p & 1) * 2 + h) * STB;
                const uint32_t bb = ab + AST;
                #pragma unroll
                for (int ks = 0; ks < 4; ks++) {
                    uint32_t af[4][4], bf[4][4];
                    #pragma unroll
                    for (int mt = 0; mt < 4; mt++) {
                        int row = wm * 64 + mt * 16 + (mat & 1) * 8 + mr;
                        uint32_t off = (uint32_t)(row << 7) + ks * 32 + (mat >> 1) * 16;
                        uint32_t sw = off ^ ((off >> 3) & 0x70);
                        ldm_x4(af[mt], ab + sw);
                    }
                    #pragma unroll
                    for (int bq = 0; bq < 4; bq++) {
                        int nrow = wn * 64 + (bq * 2 + (mat >> 1)) * 8 + mr;
                        uint32_t off = (uint32_t)(nrow << 7) + ks * 32 + (mat & 1) * 16;
                        uint32_t sw = off ^ ((off >> 3) & 0x70);
                        ldm_x4(bf[bq], bb + sw);
                    }
                    if (h == 0 && ks == 0) {
                        // fold interleaved with first mma group of the pair:
                        // FMULs of tile i+1 issue under the HMMA shadow of tile i
                        #pragma unroll
                        for (int mt = 0; mt < 4; mt++)
                            #pragma unroll
                            for (int nt = 0; nt < 8; nt++) {
                                acc[mt][nt][0] *= rr;
                                acc[mt][nt][1] *= rr;
                                acc[mt][nt][2] *= rr;
                                acc[mt][nt][3] *= rr;
                                mma_f16(acc[mt][nt], af[mt], &bf[nt >> 1][(nt & 1) * 2]);
                            }
                    } else {
                        #pragma unroll
                        for (int mt = 0; mt < 4; mt++)
                            #pragma unroll
                            for (int nt = 0; nt < 8; nt++)
                                mma_f16(acc[mt][nt], af[mt], &bf[nt >> 1][(nt & 1) * 2]);
                    }
                }
            }
        }

        // epilogue: scale by this warp's last block S; fp16 or fp32 stores
        if (out_half) {
            __half* Ch = (__half*)Cv;
            #pragma unroll
            for (int mt = 0; mt < 4; mt++) {
                int r0 = bm * BM + wm * 64 + mt * 16 + g;
                #pragma unroll
                for (int nt = 0; nt < 8; nt++) {
                    int c0 = bn * BN + wn * 64 + nt * 8 + t4 * 2;
                    __half2 h0 = __floats2half2_rn(acc[mt][nt][0] * s_cur, acc[mt][nt][1] * s_cur);
                    __half2 h1 = __floats2half2_rn(acc[mt][nt][2] * s_cur, acc[mt][nt][3] * s_cur);
                    *reinterpret_cast<__half2*>(&Ch[(size_t)r0 * N + c0]) = h0;
                    *reinterpret_cast<__half2*>(&Ch[(size_t)(r0 + 8) * N + c0]) = h1;
                }
            }
        } else {
            float* Cf = (float*)Cv;
            #pragma unroll
            for (int mt = 0; mt < 4; mt++) {
                int r0 = bm * BM + wm * 64 + mt * 16 + g;
                #pragma unroll
                for (int nt = 0; nt < 8; nt++) {
                    int c0 = bn * BN + wn * 64 + nt * 8 + t4 * 2;
                    float2 v0 = make_float2(acc[mt][nt][0] * s_cur, acc[mt][nt][1] * s_cur);
                    float2 v1 = make_float2(acc[mt][nt][2] * s_cur, acc[mt][nt][3] * s_cur);
                    *reinterpret_cast<float2*>(&Cf[(size_t)r0 * N + c0]) = v0;
                    *reinterpret_cast<float2*>(&Cf[(size_t)(r0 + 8) * N + c0]) = v1;
                }
            }
        }
    }
}

// ---------------- launch ----------------
extern "C" void kernel_launch(void* const* d_in, const int* in_sizes, int n_in,
                              void* d_out, int out_size) {
    (void)in_sizes; (void)n_in; (void)out_size;
    const float* x   = (const float*)d_in[0];
    const float* w1q = (const float*)d_in[1];
    const float* w1s = (const float*)d_in[2];
    const float* w3q = (const float*)d_in[3];
    const float* w3s = (const float*)d_in[4];
    const float* w2q = (const float*)d_in[5];
    const float* w2s = (const float*)d_in[6];
    float* out = (float*)d_out;

    __half *xh, *w1h, *w3h, *w2h, *gh, *uh, *acth;
    cudaGetSymbolAddress((void**)&xh,   d_xh);
    cudaGetSymbolAddress((void**)&w1h,  d_w1h);
    cudaGetSymbolAddress((void**)&w3h,  d_w3h);
    cudaGetSymbolAddress((void**)&w2h,  d_w2h);
    cudaGetSymbolAddress((void**)&gh,   d_gh);
    cudaGetSymbolAddress((void**)&uh,   d_uh);
    cudaGetSymbolAddress((void**)&acth, d_acth);

    int nsm = 148;
    cudaDeviceGetAttribute(&nsm, cudaDevAttrMultiProcessorCount, 0);

    cudaFuncSetAttribute(gemm_f16, cudaFuncAttributeMaxDynamicSharedMemorySize, SMEMB);

    // one fused convert launch: x + w1 + w3 + w2 (4 float4 per thread)
    const int n4tot = N4X + 3 * N4W;
    cvt_all_kernel<<<(n4tot + 1023) / 1024, 256>>>(
        (const float4*)x,   (uint2*)xh,
        (const float4*)w1q, (uint2*)w1h,
        (const float4*)w3q, (uint2*)w3h,
        (const float4*)w2q, (uint2*)w2h, n4tot);

    // g = x@w1^T and u = x@w3^T in ONE persistent launch (fp16 outputs)
    {
        const int tiles = (TDIM / BM) * (FDIM / BN) * 2;
        const int grid = tiles < nsm ? tiles : nsm;
        gemm_f16<<<grid, 256, SMEMB>>>(
            xh, w1h, w1s, gh, w3h, w3s, uh, TDIM, FDIM, HDIM, 1, 2);
    }

    const int n4f = TDIM * FDIM / 4;
    silu_mul_h_kernel<<<(n4f + 1023) / 1024, 256>>>(
        (const uint2*)gh, (const uint2*)uh, (uint2*)acth, n4f);

    // out = act @ w2^T  (fp32 out, persistent)
    {
        const int tiles = (TDIM / BM) * (HDIM / BN);
        const int grid = tiles < nsm ? tiles : nsm;
        gemm_f16<<<grid, 256, SMEMB>>>(
            acth, w2h, w2s, out, w2h, w2s, out, TDIM, HDIM, FDIM, 0, 1);
    }
}